// round 6
// baseline (speedup 1.0000x reference)
#include <cuda_runtime.h>
#include <cuda_bf16.h>

// DrugBAN fused kernel, R5: R3 balanced grid + 256-bit evict_last loads.
//
// Algebra (verified, rel_err ~2e-7): softmax rows sum to 1, so
//   drug_ctx[b,:] = (1/NT) * segment_sum(drug_x)  (rank < NMAX only)
//   tgt_ctx[b,:]  = mean_t target_h[b,t,:]
// W_a / GEMM / softmax cancel.
//
// R4 failed to compile: sm_100 ptxas requires .v8.b32/.v4.b64 with
// .L2::evict_last. R5 widens all input loads to 256-bit v8.b32 with the
// hint (legal + halves LDG count). Working set 80 MB < L2 ~126 MB; graph
// replays should then be served from L2 instead of HBM.
//
// Inputs: d_in[0] drug_x f32[16384,256], d_in[1] batch_idx i32[16384] sorted,
//         d_in[2] target_h f32[64,1024,256], d_in[3] W_a (unused).
// Output: f32 [64, 512] = [drug_ctx | tgt_ctx].

#define NT_LEN   1024
#define NMAX_CAP 512
#define BATCH_B  64
#define TCHUNKS  3

__device__ float g_partial[BATCH_B * 4 * TCHUNKS * 64];
__device__ int   g_ticket[BATCH_B * 4];   // zero-init; self-resetting

struct f8 { float4 a, b; };

__device__ __forceinline__ f8 ldg_el8(const float* p) {
    f8 v;
    asm("ld.global.nc.L2::evict_last.v8.b32 {%0,%1,%2,%3,%4,%5,%6,%7}, [%8];"
        : "=f"(v.a.x), "=f"(v.a.y), "=f"(v.a.z), "=f"(v.a.w),
          "=f"(v.b.x), "=f"(v.b.y), "=f"(v.b.z), "=f"(v.b.w)
        : "l"(p));
    return v;
}

__device__ __forceinline__ void f8_add(f8& d, const f8& s) {
    d.a.x += s.a.x; d.a.y += s.a.y; d.a.z += s.a.z; d.a.w += s.a.w;
    d.b.x += s.b.x; d.b.y += s.b.y; d.b.z += s.b.z; d.b.w += s.b.w;
}

__device__ __forceinline__ int lb_search(const int* __restrict__ a, int n, int key) {
    int lo = 0, hi = n;
    while (lo < hi) {
        int mid = (lo + hi) >> 1;
        if (__ldg(a + mid) < key) lo = mid + 1; else hi = mid;
    }
    return lo;
}

// reduce 256 f8 entries (8 cols x 32 rowgroups, stride-8) down to 8 cols
__device__ __forceinline__ void block_reduce_8(f8* red, int tid) {
    __syncthreads();
    #pragma unroll
    for (int s = 128; s >= 8; s >>= 1) {
        if (tid < s) {
            f8 m = red[tid];
            f8_add(m, red[tid + s]);
            red[tid] = m;
        }
        __syncthreads();
    }
}

__global__ __launch_bounds__(256, 8)
void drugban_fused_kernel(const float* __restrict__ drug_x,
                          const int*   __restrict__ batch_idx,
                          const float* __restrict__ target_h,
                          float*       __restrict__ out,
                          int n_nodes) {
    const int b    = blockIdx.x;     // batch 0..63
    const int part = blockIdx.y;     // 0..3 drug quarters, 4..15 target (q,c)
    const int tid  = threadIdx.x;    // 256 threads
    const int col  = tid & 7;        // 32B column within the 256B slice row
    const int rg   = tid >> 3;       // 0..31 row group

    __shared__ f8 red[256];          // 8 KB
    __shared__ int s_ticket;

    const float scale = 1.0f / (float)NT_LEN;
    f8 acc;
    acc.a = make_float4(0.f, 0.f, 0.f, 0.f);
    acc.b = make_float4(0.f, 0.f, 0.f, 0.f);

    if (part < 4) {
        // ---- drug segment sum, dims [part*64, +64) ----
        int start = lb_search(batch_idx, n_nodes, b);
        int end   = lb_search(batch_idx, n_nodes, b + 1);
        if (end - start > NMAX_CAP) end = start + NMAX_CAP;

        // row = 256 floats; slice row = 64 floats at part*64; col*8 within it
        const float* base = drug_x + (size_t)part * 64 + (size_t)col * 8;
        for (int i = start + rg; i < end; i += 32) {
            f8 v = ldg_el8(base + (size_t)i * 256);
            f8_add(acc, v);
        }

        red[tid] = acc;
        block_reduce_8(red, tid);

        if (tid < 8) {
            f8 r = red[tid];
            r.a.x *= scale; r.a.y *= scale; r.a.z *= scale; r.a.w *= scale;
            r.b.x *= scale; r.b.y *= scale; r.b.z *= scale; r.b.w *= scale;
            float4* o = reinterpret_cast<float4*>(out + b * 512 + part * 64 + tid * 8);
            o[0] = r.a; o[1] = r.b;
        }
    } else {
        // ---- target partial sum: quarter q, t-chunk c ----
        const int idx = part - 4;
        const int q = idx & 3;
        const int c = idx >> 2;
        const int t0 = (c * NT_LEN) / TCHUNKS;
        const int t1 = ((c + 1) * NT_LEN) / TCHUNKS;

        const float* base = target_h + (size_t)b * (NT_LEN * 256)
                            + (size_t)q * 64 + (size_t)col * 8;
        #pragma unroll 2
        for (int t = t0 + rg; t < t1; t += 32) {
            f8 v = ldg_el8(base + (size_t)t * 256);
            f8_add(acc, v);
        }

        red[tid] = acc;
        block_reduce_8(red, tid);

        // write partial (unscaled) to scratch
        if (tid < 8) {
            float4* pslot = reinterpret_cast<float4*>(
                g_partial + (((b * 4 + q) * TCHUNKS + c) * 64) + tid * 8);
            pslot[0] = red[tid].a; pslot[1] = red[tid].b;
        }

        __threadfence();
        __syncthreads();
        if (tid == 0) s_ticket = atomicAdd(&g_ticket[b * 4 + q], 1);
        __syncthreads();

        if (s_ticket == TCHUNKS - 1) {
            __threadfence();  // acquire peers' partials
            if (tid < 16) {
                const float4* pbase = reinterpret_cast<const float4*>(
                    g_partial + ((b * 4 + q) * TCHUNKS * 64));
                // fixed order c = 0,1,2 -> deterministic
                float4 r  = pbase[tid];
                float4 p1 = pbase[16 + tid];
                float4 p2 = pbase[32 + tid];
                r.x = (r.x + p1.x + p2.x) * scale;
                r.y = (r.y + p1.y + p2.y) * scale;
                r.z = (r.z + p1.z + p2.z) * scale;
                r.w = (r.w + p1.w + p2.w) * scale;
                reinterpret_cast<float4*>(out + b * 512 + 256 + q * 64)[tid] = r;
            }
            if (tid == 0) g_ticket[b * 4 + q] = 0;  // reset for next replay
        }
    }
}

extern "C" void kernel_launch(void* const* d_in, const int* in_sizes, int n_in,
                              void* d_out, int out_size) {
    const float* drug_x    = (const float*)d_in[0];
    const int*   batch_idx = (const int*)d_in[1];
    const float* target_h  = (const float*)d_in[2];
    // d_in[3] (W_a) cancels out mathematically; unused.
    float* out = (float*)d_out;
    int n_nodes = in_sizes[1];

    dim3 grid(BATCH_B, 4 + 4 * TCHUNKS);   // 64 x 16 = 1024 uniform blocks
    drugban_fused_kernel<<<grid, 256>>>(drug_x, batch_idx, target_h, out, n_nodes);
}